// round 3
// baseline (speedup 1.0000x reference)
#include <cuda_runtime.h>
#include <cstdint>

// Problem constants (fixed by the reference)
#define NNODES 50000
#define NREL   4
#define NEDGES 250000
#define INF    512
#define HIDF   512
#define OUTF   256

// -------- scratch (device globals: no allocation in kernel_launch) --------
__device__ __align__(16) float g_H1[(size_t)NNODES * HIDF];   // layer-1 activations (pre-relu)
__device__ __align__(16) float g_Y [(size_t)NNODES * HIDF];   // per-relation GEMM temp
__device__ __align__(16) float g_invdeg[NREL * NNODES];       // 1/max(deg,1) per relation
__device__ __align__(16) float g_Ws1[INF * HIDF];             // sum_r Wself1[r]
__device__ __align__(16) float g_bs1[HIDF];
__device__ __align__(16) float g_Ws2[HIDF * OUTF];            // sum_r Wself2[r]
__device__ __align__(16) float g_bs2[OUTF];
__device__ __align__(16) int   g_src32[NREL * NEDGES];        // edge src as int32
__device__ __align__(16) int   g_dst32[NREL * NEDGES];        // edge dst as int32
__device__ int g_is64;                                        // edge dtype flag

// ---------------------------------------------------------------------------
// edge dtype detection + conversion (int64 vs int32, decided on device)
// ---------------------------------------------------------------------------
__global__ void k_detect(const unsigned* __restrict__ w) {
    if (threadIdx.x == 0 && blockIdx.x == 0) {
        unsigned acc = 0;
        // if data is int64 with values < 2^31, every odd 32-bit word is 0
        for (int i = 0; i < 64; i++) acc |= w[2 * i + 1];
        g_is64 = (acc == 0) ? 1 : 0;
    }
}

__global__ void k_cvt(const void* __restrict__ p, int* __restrict__ out, int n) {
    int i = blockIdx.x * blockDim.x + threadIdx.x;
    if (i >= n) return;
    if (g_is64) out[i] = (int)((const long long*)p)[i];
    else        out[i] = ((const int*)p)[i];
}

// ---------------------------------------------------------------------------
// small prep kernels
// ---------------------------------------------------------------------------
__global__ void k_zero(float* __restrict__ p, int n) {
    int i = blockIdx.x * blockDim.x + threadIdx.x;
    if (i < n) p[i] = 0.0f;
}

// deg[r*N + dst] += 1 over all relations' edges.  dst layout: [NREL, NEDGES]
__global__ void k_count(const int* __restrict__ dst, float* __restrict__ deg) {
    int i = blockIdx.x * blockDim.x + threadIdx.x;
    if (i >= NREL * NEDGES) return;
    int r = i / NEDGES;
    int d = dst[i];
    atomicAdd(&deg[r * NNODES + d], 1.0f);
}

__global__ void k_invert(float* __restrict__ deg, int n) {
    int i = blockIdx.x * blockDim.x + threadIdx.x;
    if (i < n) deg[i] = 1.0f / fmaxf(deg[i], 1.0f);
}

// out[i] = sum_r W[r*sz + i]
__global__ void k_sumw(const float* __restrict__ W, float* __restrict__ out, int sz) {
    int i = blockIdx.x * blockDim.x + threadIdx.x;
    if (i >= sz) return;
    float s = 0.0f;
#pragma unroll
    for (int r = 0; r < NREL; r++) s += W[(size_t)r * sz + i];
    out[i] = s;
}

// ---------------------------------------------------------------------------
// fp32 SGEMM: C[M,N] = op(A)[M,K] @ B[K,N] (+ bias[N]); op = relu if RELU_A
// BM=128, BN=128, BK=8, 256 threads, 8x8 per-thread microtile
// ---------------------------------------------------------------------------
template <int RELU_A, int HAS_BIAS>
__global__ __launch_bounds__(256, 2) void k_sgemm(
    const float* __restrict__ A, const float* __restrict__ B,
    float* __restrict__ C, const float* __restrict__ bias,
    int M, int N, int K)
{
    __shared__ float As[8][128];
    __shared__ float Bs[8][128];

    const int tid = threadIdx.x;
    const int tx  = tid & 15;   // 0..15 -> 8 cols each
    const int ty  = tid >> 4;   // 0..15 -> 8 rows each
    const int bm  = blockIdx.y * 128;
    const int bn  = blockIdx.x * 128;

    // load mapping
    const int aRow = tid >> 1;          // 0..127
    const int aK   = (tid & 1) << 2;    // 0 or 4
    const int bRow = tid >> 5;          // 0..7
    const int bCol = (tid & 31) << 2;   // 0..124

    const float* Ap = A + (size_t)(bm + aRow) * K + aK;
    const float* Bp = B + (size_t)bRow * N + bn + bCol;
    const bool aOk  = (bm + aRow) < M;

    float acc[8][8];
#pragma unroll
    for (int i = 0; i < 8; i++)
#pragma unroll
        for (int j = 0; j < 8; j++) acc[i][j] = 0.0f;

    for (int k0 = 0; k0 < K; k0 += 8) {
        float4 av = aOk ? *(const float4*)Ap : make_float4(0.f, 0.f, 0.f, 0.f);
        if (RELU_A) {
            av.x = fmaxf(av.x, 0.f); av.y = fmaxf(av.y, 0.f);
            av.z = fmaxf(av.z, 0.f); av.w = fmaxf(av.w, 0.f);
        }
        As[aK + 0][aRow] = av.x;
        As[aK + 1][aRow] = av.y;
        As[aK + 2][aRow] = av.z;
        As[aK + 3][aRow] = av.w;
        *(float4*)&Bs[bRow][bCol] = *(const float4*)Bp;
        __syncthreads();

#pragma unroll
        for (int kk = 0; kk < 8; kk++) {
            float4 a0 = *(const float4*)&As[kk][ty * 8];
            float4 a1 = *(const float4*)&As[kk][ty * 8 + 4];
            float4 b0 = *(const float4*)&Bs[kk][tx * 8];
            float4 b1 = *(const float4*)&Bs[kk][tx * 8 + 4];
            float a[8] = {a0.x, a0.y, a0.z, a0.w, a1.x, a1.y, a1.z, a1.w};
            float b[8] = {b0.x, b0.y, b0.z, b0.w, b1.x, b1.y, b1.z, b1.w};
#pragma unroll
            for (int i = 0; i < 8; i++)
#pragma unroll
                for (int j = 0; j < 8; j++) acc[i][j] = fmaf(a[i], b[j], acc[i][j]);
        }
        __syncthreads();

        Ap += 8;
        Bp += (size_t)8 * N;
    }

#pragma unroll
    for (int i = 0; i < 8; i++) {
        int row = bm + ty * 8 + i;
        if (row < M) {
            float* Cp = C + (size_t)row * N + bn + tx * 8;
#pragma unroll
            for (int j = 0; j < 8; j += 4) {
                float4 v = make_float4(acc[i][j], acc[i][j + 1], acc[i][j + 2], acc[i][j + 3]);
                if (HAS_BIAS) {
                    float4 bb = *(const float4*)&bias[bn + tx * 8 + j];
                    v.x += bb.x; v.y += bb.y; v.z += bb.z; v.w += bb.w;
                }
                *(float4*)(Cp + j) = v;
            }
        }
    }
}

// ---------------------------------------------------------------------------
// scatter-add: out[dst[e], :] += Y[src[e], :] * invdeg[dst[e]]   (F floats/row)
// one thread = one float4 of one edge; 4 scalar RED.E.ADD.F32 per thread
// ---------------------------------------------------------------------------
template <int F>
__global__ void k_scatter(const float* __restrict__ Y,
                          const int* __restrict__ src,
                          const int* __restrict__ dst,
                          const float* __restrict__ invdeg,
                          float* __restrict__ out)
{
    constexpr int FV = F / 4;           // float4s per row
    unsigned gid = blockIdx.x * blockDim.x + threadIdx.x;
    if (gid >= (unsigned)NEDGES * FV) return;
    unsigned e = gid / FV;
    unsigned f = (gid - e * FV) << 2;

    int s = src[e];
    int d = dst[e];
    float w = invdeg[d];

    float4 v = *(const float4*)(Y + (size_t)s * F + f);
    float* o = out + (size_t)d * F + f;
    atomicAdd(o + 0, v.x * w);
    atomicAdd(o + 1, v.y * w);
    atomicAdd(o + 2, v.z * w);
    atomicAdd(o + 3, v.w * w);
}

// ---------------------------------------------------------------------------
// launch
// ---------------------------------------------------------------------------
extern "C" void kernel_launch(void* const* d_in, const int* in_sizes, int n_in,
                              void* d_out, int out_size)
{
    const float* x       = (const float*)d_in[0];
    const float* Wself1  = (const float*)d_in[1];
    const float* Wneigh1 = (const float*)d_in[2];
    const float* b1      = (const float*)d_in[3];
    const float* Wself2  = (const float*)d_in[4];
    const float* Wneigh2 = (const float*)d_in[5];
    const float* b2      = (const float*)d_in[6];
    const void*  esrc    = d_in[7];
    const void*  edst    = d_in[8];
    float*       out     = (float*)d_out;

    float *H1, *Y, *invdeg, *Ws1, *bs1, *Ws2, *bs2;
    int *src32, *dst32;
    cudaGetSymbolAddress((void**)&H1,     g_H1);
    cudaGetSymbolAddress((void**)&Y,      g_Y);
    cudaGetSymbolAddress((void**)&invdeg, g_invdeg);
    cudaGetSymbolAddress((void**)&Ws1,    g_Ws1);
    cudaGetSymbolAddress((void**)&bs1,    g_bs1);
    cudaGetSymbolAddress((void**)&Ws2,    g_Ws2);
    cudaGetSymbolAddress((void**)&bs2,    g_bs2);
    cudaGetSymbolAddress((void**)&src32,  g_src32);
    cudaGetSymbolAddress((void**)&dst32,  g_dst32);

    const int T = 256;
    const int NE = NREL * NEDGES;

    // detect edge dtype (int32 vs int64) on device, then convert to int32
    k_detect<<<1, 32>>>((const unsigned*)esrc);
    k_cvt<<<(NE + T - 1) / T, T>>>(esrc, src32, NE);
    k_cvt<<<(NE + T - 1) / T, T>>>(edst, dst32, NE);

    // degrees -> inverse degrees (shared by both layers)
    k_zero<<<(NREL * NNODES + T - 1) / T, T>>>(invdeg, NREL * NNODES);
    k_count<<<(NE + T - 1) / T, T>>>(dst32, invdeg);
    k_invert<<<(NREL * NNODES + T - 1) / T, T>>>(invdeg, NREL * NNODES);

    // summed self-weights / biases
    k_sumw<<<(INF * HIDF + T - 1) / T, T>>>(Wself1, Ws1, INF * HIDF);
    k_sumw<<<(HIDF + T - 1) / T, T>>>(b1, bs1, HIDF);
    k_sumw<<<(HIDF * OUTF + T - 1) / T, T>>>(Wself2, Ws2, HIDF * OUTF);
    k_sumw<<<(OUTF + T - 1) / T, T>>>(b2, bs2, OUTF);

    const int MB = (NNODES + 127) / 128;

    // -------- layer 1 --------
    {
        dim3 grid(HIDF / 128, MB);
        // self term (init H1 with bias)
        k_sgemm<0, 1><<<grid, T>>>(x, Ws1, H1, bs1, NNODES, HIDF, INF);
        // neighbor terms, one relation at a time
        for (int r = 0; r < NREL; r++) {
            k_sgemm<0, 0><<<grid, T>>>(x, Wneigh1 + (size_t)r * INF * HIDF, Y, nullptr,
                                       NNODES, HIDF, INF);
            unsigned work = (unsigned)NEDGES * (HIDF / 4);
            k_scatter<HIDF><<<(work + T - 1) / T, T>>>(Y, src32 + (size_t)r * NEDGES,
                                                       dst32 + (size_t)r * NEDGES,
                                                       invdeg + r * NNODES, H1);
        }
    }

    // -------- layer 2 (relu fused into GEMM A-reads) --------
    {
        dim3 grid(OUTF / 128, MB);
        k_sgemm<1, 1><<<grid, T>>>(H1, Ws2, out, bs2, NNODES, OUTF, HIDF);
        for (int r = 0; r < NREL; r++) {
            k_sgemm<1, 0><<<grid, T>>>(H1, Wneigh2 + (size_t)r * HIDF * OUTF, Y, nullptr,
                                       NNODES, OUTF, HIDF);
            unsigned work = (unsigned)NEDGES * (OUTF / 4);
            k_scatter<OUTF><<<(work + T - 1) / T, T>>>(Y, src32 + (size_t)r * NEDGES,
                                                       dst32 + (size_t)r * NEDGES,
                                                       invdeg + r * NNODES, out);
        }
    }
}

// round 4
// speedup vs baseline: 1.7732x; 1.7732x over previous
#include <cuda_runtime.h>
#include <cuda_bf16.h>
#include <cstdint>

// Problem constants (fixed by the reference)
#define NNODES 50000
#define NREL   4
#define NEDGES 250000
#define INF    512
#define HIDF   512
#define OUTF   256

typedef __nv_bfloat16 bf16;

// -------- scratch (device globals: no allocation in kernel_launch) --------
__device__ __align__(16) float g_H1[(size_t)NNODES * HIDF];   // layer-1 activations (pre-relu)
__device__ __align__(16) float g_Y [(size_t)NNODES * HIDF];   // per-relation GEMM temp
__device__ __align__(16) float g_invdeg[NREL * NNODES];       // 1/max(deg,1) per relation
__device__ __align__(16) float g_Ws1[INF * HIDF];             // sum_r Wself1[r] (fp32 temp)
__device__ __align__(16) float g_bs1[HIDF];
__device__ __align__(16) float g_Ws2[HIDF * OUTF];            // sum_r Wself2[r] (fp32 temp)
__device__ __align__(16) float g_bs2[OUTF];
__device__ __align__(16) int   g_src32[NREL * NEDGES];
__device__ __align__(16) int   g_dst32[NREL * NEDGES];
__device__ int g_is64;

// bf16 hi/lo splits
__device__ __align__(16) bf16 g_Xhi[(size_t)NNODES * INF];
__device__ __align__(16) bf16 g_Xlo[(size_t)NNODES * INF];
__device__ __align__(16) bf16 g_Hhi[(size_t)NNODES * HIDF];
__device__ __align__(16) bf16 g_Hlo[(size_t)NNODES * HIDF];
// weights: [Ws1, Wn1_0..3] each 512x512, then [Ws2, Wn2_0..3] each 512x256
#define W_L1_SZ (512 * 512)
#define W_L2_SZ (512 * 256)
#define W_L2_OFF (5 * W_L1_SZ)
#define W_TOT (5 * W_L1_SZ + 5 * W_L2_SZ)
__device__ __align__(16) bf16 g_Whi[W_TOT];
__device__ __align__(16) bf16 g_Wlo[W_TOT];

// ---------------------------------------------------------------------------
// edge dtype detection + conversion
// ---------------------------------------------------------------------------
__global__ void k_detect(const unsigned* __restrict__ w) {
    if (threadIdx.x == 0 && blockIdx.x == 0) {
        unsigned acc = 0;
        for (int i = 0; i < 64; i++) acc |= w[2 * i + 1];
        g_is64 = (acc == 0) ? 1 : 0;
    }
}

__global__ void k_cvt(const void* __restrict__ p, int* __restrict__ out, int n) {
    int i = blockIdx.x * blockDim.x + threadIdx.x;
    if (i >= n) return;
    if (g_is64) out[i] = (int)((const long long*)p)[i];
    else        out[i] = ((const int*)p)[i];
}

// ---------------------------------------------------------------------------
// small prep kernels
// ---------------------------------------------------------------------------
__global__ void k_zero(float* __restrict__ p, int n) {
    int i = blockIdx.x * blockDim.x + threadIdx.x;
    if (i < n) p[i] = 0.0f;
}

__global__ void k_count(const int* __restrict__ dst, float* __restrict__ deg) {
    int i = blockIdx.x * blockDim.x + threadIdx.x;
    if (i >= NREL * NEDGES) return;
    int r = i / NEDGES;
    atomicAdd(&deg[r * NNODES + dst[i]], 1.0f);
}

__global__ void k_invert(float* __restrict__ deg, int n) {
    int i = blockIdx.x * blockDim.x + threadIdx.x;
    if (i < n) deg[i] = 1.0f / fmaxf(deg[i], 1.0f);
}

__global__ void k_sumw(const float* __restrict__ W, float* __restrict__ out, int sz) {
    int i = blockIdx.x * blockDim.x + threadIdx.x;
    if (i >= sz) return;
    float s = 0.0f;
#pragma unroll
    for (int r = 0; r < NREL; r++) s += W[(size_t)r * sz + i];
    out[i] = s;
}

// fp32 -> (hi, lo) bf16 split, optional relu first
__global__ void k_split(const float* __restrict__ in, bf16* __restrict__ hi,
                        bf16* __restrict__ lo, size_t n, int relu) {
    size_t i = (size_t)blockIdx.x * blockDim.x + threadIdx.x;
    if (i >= n) return;
    float v = in[i];
    if (relu) v = fmaxf(v, 0.0f);
    bf16 h = __float2bfloat16(v);
    hi[i] = h;
    lo[i] = __float2bfloat16(v - __bfloat162float(h));
}

// ---------------------------------------------------------------------------
// bf16x3 tensor-core GEMM: C[M,N] = (Ahi+Alo)[M,K] @ (Bhi+Blo)[K,N] (+bias)
// BM=128, BN=128, BK=32, 256 threads, warp tile 64x32, mma.m16n8k16
// double-buffered cp.async, dynamic smem
// ---------------------------------------------------------------------------
#define GBM 128
#define GBN 128
#define GBK 32
#define SA_STRIDE 40
#define SB_STRIDE 136
#define SA_BYTES (2 * 2 * 128 * SA_STRIDE * 2)   // 40960
#define SB_BYTES (2 * 2 * 32 * SB_STRIDE * 2)    // 34816
#define GEMM_SMEM (SA_BYTES + SB_BYTES)          // 75776

__device__ __forceinline__ void cp16(uint32_t dst, const void* src, bool pred) {
    int sz = pred ? 16 : 0;
    asm volatile("cp.async.cg.shared.global [%0], [%1], 16, %2;"
                 :: "r"(dst), "l"(src), "r"(sz));
}
__device__ __forceinline__ void ldsm_x4(uint32_t* r, uint32_t addr) {
    asm volatile("ldmatrix.sync.aligned.m8n8.x4.shared.b16 {%0,%1,%2,%3}, [%4];"
                 : "=r"(r[0]), "=r"(r[1]), "=r"(r[2]), "=r"(r[3]) : "r"(addr));
}
__device__ __forceinline__ void ldsm_x4t(uint32_t* r, uint32_t addr) {
    asm volatile("ldmatrix.sync.aligned.m8n8.x4.trans.shared.b16 {%0,%1,%2,%3}, [%4];"
                 : "=r"(r[0]), "=r"(r[1]), "=r"(r[2]), "=r"(r[3]) : "r"(addr));
}
__device__ __forceinline__ void mma_bf16(float* c, const uint32_t* a, const uint32_t* b) {
    asm volatile(
        "mma.sync.aligned.m16n8k16.row.col.f32.bf16.bf16.f32 "
        "{%0,%1,%2,%3}, {%4,%5,%6,%7}, {%8,%9}, {%0,%1,%2,%3};"
        : "+f"(c[0]), "+f"(c[1]), "+f"(c[2]), "+f"(c[3])
        : "r"(a[0]), "r"(a[1]), "r"(a[2]), "r"(a[3]), "r"(b[0]), "r"(b[1]));
}

template <int HAS_BIAS>
__global__ void __launch_bounds__(256, 1) k_mma(
    const bf16* __restrict__ Ahi, const bf16* __restrict__ Alo,
    const bf16* __restrict__ Bhi, const bf16* __restrict__ Blo,
    float* __restrict__ C, const float* __restrict__ bias,
    int M, int N, int K)
{
    extern __shared__ __align__(16) char smem_raw[];
    bf16* sA = (bf16*)smem_raw;                     // [stage][h][128][SA_STRIDE]
    bf16* sB = (bf16*)(smem_raw + SA_BYTES);        // [stage][h][32][SB_STRIDE]

    const int tid  = threadIdx.x;
    const int lane = tid & 31;
    const int warp = tid >> 5;
    const int bm   = blockIdx.y * GBM;
    const int bn   = blockIdx.x * GBN;
    const int m_base = (warp & 1) * 64;
    const int n_base = (warp >> 1) * 32;

    const uint32_t sA_u = (uint32_t)__cvta_generic_to_shared(sA);
    const uint32_t sB_u = (uint32_t)__cvta_generic_to_shared(sB);

    const bf16* Ag[2] = {Ahi, Alo};
    const bf16* Bg[2] = {Bhi, Blo};

    auto load_tile = [&](int kt, int stage) {
        const int k0 = kt * GBK;
        // A: per h, 512 chunks of 16B (row=c>>2, col=(c&3)*8)
#pragma unroll
        for (int h = 0; h < 2; h++) {
#pragma unroll
            for (int i = 0; i < 2; i++) {
                int c = tid + i * 256;
                int row = c >> 2, col = (c & 3) * 8;
                int rg = bm + row;
                bool ok = rg < M;
                int rc = ok ? rg : (M - 1);
                uint32_t dst = sA_u + (((stage * 2 + h) * 128 + row) * SA_STRIDE + col) * 2;
                cp16(dst, Ag[h] + (size_t)rc * K + k0 + col, ok);
            }
        }
        // B: per h, 512 chunks (row=c>>4, col=(c&15)*8); K,N multiples of tile
#pragma unroll
        for (int h = 0; h < 2; h++) {
#pragma unroll
            for (int i = 0; i < 2; i++) {
                int c = tid + i * 256;
                int row = c >> 4, col = (c & 15) * 8;
                uint32_t dst = sB_u + (((stage * 2 + h) * 32 + row) * SB_STRIDE + col) * 2;
                cp16(dst, Bg[h] + (size_t)(k0 + row) * N + bn + col, true);
            }
        }
    };

    float acc[4][4][4];
#pragma unroll
    for (int i = 0; i < 4; i++)
#pragma unroll
        for (int j = 0; j < 4; j++)
#pragma unroll
            for (int k = 0; k < 4; k++) acc[i][j][k] = 0.0f;

    const int KT = K >> 5;

    load_tile(0, 0);
    asm volatile("cp.async.commit_group;");

    for (int kt = 0; kt < KT; kt++) {
        const int stage = kt & 1;
        if (kt + 1 < KT) {
            load_tile(kt + 1, (kt + 1) & 1);
            asm volatile("cp.async.commit_group;");
            asm volatile("cp.async.wait_group 1;");
        } else {
            asm volatile("cp.async.wait_group 0;");
        }
        __syncthreads();

#pragma unroll
        for (int ks = 0; ks < 2; ks++) {
            const int k0s = ks * 16;
            uint32_t afr[2][4][4];
#pragma unroll
            for (int h = 0; h < 2; h++)
#pragma unroll
                for (int am = 0; am < 4; am++) {
                    int row = m_base + am * 16 + (lane & 15);
                    int col = k0s + 8 * (lane >> 4);
                    uint32_t addr = sA_u + (((stage * 2 + h) * 128 + row) * SA_STRIDE + col) * 2;
                    ldsm_x4(afr[h][am], addr);
                }
            uint32_t bfr[2][4][2];
#pragma unroll
            for (int h = 0; h < 2; h++)
#pragma unroll
                for (int bp = 0; bp < 2; bp++) {
                    int row = k0s + (lane & 15);
                    int col = n_base + bp * 16 + 8 * (lane >> 4);
                    uint32_t addr = sB_u + (((stage * 2 + h) * 32 + row) * SB_STRIDE + col) * 2;
                    uint32_t r[4];
                    ldsm_x4t(r, addr);
                    bfr[h][bp * 2][0] = r[0]; bfr[h][bp * 2][1] = r[1];
                    bfr[h][bp * 2 + 1][0] = r[2]; bfr[h][bp * 2 + 1][1] = r[3];
                }
#pragma unroll
            for (int am = 0; am < 4; am++)
#pragma unroll
                for (int an = 0; an < 4; an++) {
                    mma_bf16(acc[am][an], afr[0][am], bfr[0][an]);  // hi*hi
                    mma_bf16(acc[am][an], afr[0][am], bfr[1][an]);  // hi*lo
                    mma_bf16(acc[am][an], afr[1][am], bfr[0][an]);  // lo*hi
                }
        }
        __syncthreads();
    }

    // epilogue
#pragma unroll
    for (int am = 0; am < 4; am++) {
#pragma unroll
        for (int an = 0; an < 4; an++) {
            int col = bn + n_base + an * 8 + (lane & 3) * 2;
            float bx = 0.f, by = 0.f;
            if (HAS_BIAS) { bx = bias[col]; by = bias[col + 1]; }
            int row0 = bm + m_base + am * 16 + (lane >> 2);
            if (row0 < M) {
                float2 v = make_float2(acc[am][an][0] + bx, acc[am][an][1] + by);
                *(float2*)&C[(size_t)row0 * N + col] = v;
            }
            int row1 = row0 + 8;
            if (row1 < M) {
                float2 v = make_float2(acc[am][an][2] + bx, acc[am][an][3] + by);
                *(float2*)&C[(size_t)row1 * N + col] = v;
            }
        }
    }
}

// ---------------------------------------------------------------------------
// scatter-add: out[dst[e], :] += Y[src[e], :] * invdeg[dst[e]]
// ---------------------------------------------------------------------------
template <int F>
__global__ void k_scatter(const float* __restrict__ Y,
                          const int* __restrict__ src,
                          const int* __restrict__ dst,
                          const float* __restrict__ invdeg,
                          float* __restrict__ out)
{
    constexpr int FV = F / 4;
    unsigned gid = blockIdx.x * blockDim.x + threadIdx.x;
    if (gid >= (unsigned)NEDGES * FV) return;
    unsigned e = gid / FV;
    unsigned f = (gid - e * FV) << 2;

    int s = src[e];
    int d = dst[e];
    float w = invdeg[d];

    float4 v = *(const float4*)(Y + (size_t)s * F + f);
    float* o = out + (size_t)d * F + f;
    atomicAdd(o + 0, v.x * w);
    atomicAdd(o + 1, v.y * w);
    atomicAdd(o + 2, v.z * w);
    atomicAdd(o + 3, v.w * w);
}

// ---------------------------------------------------------------------------
// launch
// ---------------------------------------------------------------------------
extern "C" void kernel_launch(void* const* d_in, const int* in_sizes, int n_in,
                              void* d_out, int out_size)
{
    const float* x       = (const float*)d_in[0];
    const float* Wself1  = (const float*)d_in[1];
    const float* Wneigh1 = (const float*)d_in[2];
    const float* b1      = (const float*)d_in[3];
    const float* Wself2  = (const float*)d_in[4];
    const float* Wneigh2 = (const float*)d_in[5];
    const float* b2      = (const float*)d_in[6];
    const void*  esrc    = d_in[7];
    const void*  edst    = d_in[8];
    float*       out     = (float*)d_out;

    float *H1, *Y, *invdeg, *Ws1, *bs1, *Ws2, *bs2;
    int *src32, *dst32;
    bf16 *Xhi, *Xlo, *Hhi, *Hlo, *Whi, *Wlo;
    cudaGetSymbolAddress((void**)&H1,     g_H1);
    cudaGetSymbolAddress((void**)&Y,      g_Y);
    cudaGetSymbolAddress((void**)&invdeg, g_invdeg);
    cudaGetSymbolAddress((void**)&Ws1,    g_Ws1);
    cudaGetSymbolAddress((void**)&bs1,    g_bs1);
    cudaGetSymbolAddress((void**)&Ws2,    g_Ws2);
    cudaGetSymbolAddress((void**)&bs2,    g_bs2);
    cudaGetSymbolAddress((void**)&src32,  g_src32);
    cudaGetSymbolAddress((void**)&dst32,  g_dst32);
    cudaGetSymbolAddress((void**)&Xhi,    g_Xhi);
    cudaGetSymbolAddress((void**)&Xlo,    g_Xlo);
    cudaGetSymbolAddress((void**)&Hhi,    g_Hhi);
    cudaGetSymbolAddress((void**)&Hlo,    g_Hlo);
    cudaGetSymbolAddress((void**)&Whi,    g_Whi);
    cudaGetSymbolAddress((void**)&Wlo,    g_Wlo);

    static bool attr_done = false;
    if (!attr_done) {
        cudaFuncSetAttribute(k_mma<0>, cudaFuncAttributeMaxDynamicSharedMemorySize, GEMM_SMEM);
        cudaFuncSetAttribute(k_mma<1>, cudaFuncAttributeMaxDynamicSharedMemorySize, GEMM_SMEM);
        attr_done = true;
    }

    const int T = 256;
    const int NE = NREL * NEDGES;

    // edge dtype detect + convert
    k_detect<<<1, 32>>>((const unsigned*)esrc);
    k_cvt<<<(NE + T - 1) / T, T>>>(esrc, src32, NE);
    k_cvt<<<(NE + T - 1) / T, T>>>(edst, dst32, NE);

    // degrees -> inverse degrees
    k_zero<<<(NREL * NNODES + T - 1) / T, T>>>(invdeg, NREL * NNODES);
    k_count<<<(NE + T - 1) / T, T>>>(dst32, invdeg);
    k_invert<<<(NREL * NNODES + T - 1) / T, T>>>(invdeg, NREL * NNODES);

    // summed self-weights / biases (fp32), then split everything to bf16 hi/lo
    k_sumw<<<(W_L1_SZ + T - 1) / T, T>>>(Wself1, Ws1, W_L1_SZ);
    k_sumw<<<(HIDF + T - 1) / T, T>>>(b1, bs1, HIDF);
    k_sumw<<<(W_L2_SZ + T - 1) / T, T>>>(Wself2, Ws2, W_L2_SZ);
    k_sumw<<<(OUTF + T - 1) / T, T>>>(b2, bs2, OUTF);

    k_split<<<(W_L1_SZ + T - 1) / T, T>>>(Ws1, Whi, Wlo, W_L1_SZ, 0);
    for (int r = 0; r < NREL; r++)
        k_split<<<(W_L1_SZ + T - 1) / T, T>>>(Wneigh1 + (size_t)r * W_L1_SZ,
                                              Whi + (size_t)(1 + r) * W_L1_SZ,
                                              Wlo + (size_t)(1 + r) * W_L1_SZ, W_L1_SZ, 0);
    k_split<<<(W_L2_SZ + T - 1) / T, T>>>(Ws2, Whi + W_L2_OFF, Wlo + W_L2_OFF, W_L2_SZ, 0);
    for (int r = 0; r < NREL; r++)
        k_split<<<(W_L2_SZ + T - 1) / T, T>>>(Wneigh2 + (size_t)r * W_L2_SZ,
                                              Whi + W_L2_OFF + (size_t)(1 + r) * W_L2_SZ,
                                              Wlo + W_L2_OFF + (size_t)(1 + r) * W_L2_SZ, W_L2_SZ, 0);

    // X split
    {
        size_t n = (size_t)NNODES * INF;
        k_split<<<(unsigned)((n + T - 1) / T), T>>>(x, Xhi, Xlo, n, 0);
    }

    const int MB = (NNODES + GBM - 1) / GBM;

    // -------- layer 1 --------
    {
        dim3 grid(HIDF / GBN, MB);
        k_mma<1><<<grid, T, GEMM_SMEM>>>(Xhi, Xlo, Whi, Wlo, H1, bs1, NNODES, HIDF, INF);
        for (int r = 0; r < NREL; r++) {
            k_mma<0><<<grid, T, GEMM_SMEM>>>(Xhi, Xlo,
                                             Whi + (size_t)(1 + r) * W_L1_SZ,
                                             Wlo + (size_t)(1 + r) * W_L1_SZ,
                                             Y, nullptr, NNODES, HIDF, INF);
            unsigned work = (unsigned)NEDGES * (HIDF / 4);
            k_scatter<HIDF><<<(work + T - 1) / T, T>>>(Y, src32 + (size_t)r * NEDGES,
                                                       dst32 + (size_t)r * NEDGES,
                                                       invdeg + r * NNODES, H1);
        }
    }

    // relu + split H1
    {
        size_t n = (size_t)NNODES * HIDF;
        k_split<<<(unsigned)((n + T - 1) / T), T>>>(H1, Hhi, Hlo, n, 1);
    }

    // -------- layer 2 --------
    {
        dim3 grid(OUTF / GBN, MB);
        k_mma<1><<<grid, T, GEMM_SMEM>>>(Hhi, Hlo, Whi + W_L2_OFF, Wlo + W_L2_OFF,
                                         out, bs2, NNODES, OUTF, HIDF);
        for (int r = 0; r < NREL; r++) {
            k_mma<0><<<grid, T, GEMM_SMEM>>>(Hhi, Hlo,
                                             Whi + W_L2_OFF + (size_t)(1 + r) * W_L2_SZ,
                                             Wlo + W_L2_OFF + (size_t)(1 + r) * W_L2_SZ,
                                             Y, nullptr, NNODES, OUTF, HIDF);
            unsigned work = (unsigned)NEDGES * (OUTF / 4);
            k_scatter<OUTF><<<(work + T - 1) / T, T>>>(Y, src32 + (size_t)r * NEDGES,
                                                       dst32 + (size_t)r * NEDGES,
                                                       invdeg + r * NNODES, out);
        }
    }
}

// round 5
// speedup vs baseline: 2.9265x; 1.6504x over previous
#include <cuda_runtime.h>
#include <cuda_bf16.h>
#include <cstdint>

// Problem constants (fixed by the reference)
#define NNODES 50000
#define NREL   4
#define NEDGES 250000
#define INF    512
#define HIDF   512
#define OUTF   256

#define NCHUNK 49          // ceil(50000/1024)
typedef __nv_bfloat16 bf16;

// -------- scratch (device globals: no allocation in kernel_launch) --------
__device__ __align__(16) float g_H1[(size_t)NNODES * HIDF];
__device__ __align__(16) float g_Y [(size_t)NREL * NNODES * HIDF];  // 4 planes
__device__ __align__(16) float g_Ws1[INF * HIDF];
__device__ __align__(16) float g_bs1[HIDF];
__device__ __align__(16) float g_Ws2[HIDF * OUTF];
__device__ __align__(16) float g_bs2[OUTF];
__device__ __align__(16) int   g_src32[NREL * NEDGES];
__device__ __align__(16) int   g_dst32[NREL * NEDGES];
__device__ __align__(16) int   g_deg[NREL * NNODES];
__device__ __align__(16) int   g_off[NREL * NNODES];     // exclusive offsets
__device__ __align__(16) int   g_cursor[NREL * NNODES];
__device__ __align__(16) int   g_bsum[NREL * NCHUNK];
__device__ __align__(16) int   g_lists[NREL * NEDGES];   // src ids grouped by dst
__device__ int g_is64;

// bf16 hi/lo splits
__device__ __align__(16) bf16 g_Xhi[(size_t)NNODES * INF];
__device__ __align__(16) bf16 g_Xlo[(size_t)NNODES * INF];
__device__ __align__(16) bf16 g_Hhi[(size_t)NNODES * HIDF];
__device__ __align__(16) bf16 g_Hlo[(size_t)NNODES * HIDF];
#define W_L1_SZ (512 * 512)
#define W_L2_SZ (512 * 256)
#define W_L2_OFF (5 * W_L1_SZ)
#define W_TOT (5 * W_L1_SZ + 5 * W_L2_SZ)
__device__ __align__(16) bf16 g_Whi[W_TOT];
__device__ __align__(16) bf16 g_Wlo[W_TOT];

// ---------------------------------------------------------------------------
// edge dtype detection + conversion
// ---------------------------------------------------------------------------
__global__ void k_detect(const unsigned* __restrict__ w) {
    if (threadIdx.x == 0 && blockIdx.x == 0) {
        unsigned acc = 0;
        for (int i = 0; i < 64; i++) acc |= w[2 * i + 1];
        g_is64 = (acc == 0) ? 1 : 0;
    }
}

__global__ void k_cvt2(const void* __restrict__ ps, int* __restrict__ os,
                       const void* __restrict__ pd, int* __restrict__ od, int n) {
    int i = blockIdx.x * blockDim.x + threadIdx.x;
    if (i >= n) return;
    if (g_is64) {
        os[i] = (int)((const long long*)ps)[i];
        od[i] = (int)((const long long*)pd)[i];
    } else {
        os[i] = ((const int*)ps)[i];
        od[i] = ((const int*)pd)[i];
    }
}

// ---------------------------------------------------------------------------
// CSR build: degree count -> exclusive scan -> fill lists
// ---------------------------------------------------------------------------
__global__ void k_zeroi(int* __restrict__ p, int n) {
    int i = blockIdx.x * blockDim.x + threadIdx.x;
    if (i < n) p[i] = 0;
}

__global__ void k_degcount(const int* __restrict__ dst, int* __restrict__ deg) {
    int i = blockIdx.x * blockDim.x + threadIdx.x;
    if (i >= NREL * NEDGES) return;
    int r = i / NEDGES;
    atomicAdd(&deg[r * NNODES + dst[i]], 1);
}

// per-chunk exclusive scan (1024 elems), writes chunk sums
__global__ void k_scanA(const int* __restrict__ deg, int* __restrict__ off,
                        int* __restrict__ bsum) {
    __shared__ int s[1024];
    int r = blockIdx.x / NCHUNK;
    int c = blockIdx.x % NCHUNK;
    int idx = c * 1024 + threadIdx.x;
    int v = (idx < NNODES) ? deg[r * NNODES + idx] : 0;
    s[threadIdx.x] = v;
    __syncthreads();
#pragma unroll
    for (int d = 1; d < 1024; d <<= 1) {
        int t = (threadIdx.x >= d) ? s[threadIdx.x - d] : 0;
        __syncthreads();
        s[threadIdx.x] += t;
        __syncthreads();
    }
    if (idx < NNODES) off[r * NNODES + idx] = s[threadIdx.x] - v;   // exclusive
    if (threadIdx.x == 1023) bsum[r * NCHUNK + c] = s[1023];
}

// scan the chunk sums (49 per relation) sequentially
__global__ void k_scanB(int* __restrict__ bsum) {
    int r = threadIdx.x;
    if (r >= NREL) return;
    int run = 0;
    for (int c = 0; c < NCHUNK; c++) {
        int v = bsum[r * NCHUNK + c];
        bsum[r * NCHUNK + c] = run;
        run += v;
    }
}

__global__ void k_scanC(int* __restrict__ off, const int* __restrict__ bsum) {
    int r = blockIdx.x / NCHUNK;
    int c = blockIdx.x % NCHUNK;
    int idx = c * 1024 + threadIdx.x;
    if (idx < NNODES) off[r * NNODES + idx] += bsum[r * NCHUNK + c];
}

__global__ void k_fill(const int* __restrict__ src, const int* __restrict__ dst,
                       const int* __restrict__ off, int* __restrict__ cursor,
                       int* __restrict__ lists) {
    int i = blockIdx.x * blockDim.x + threadIdx.x;
    if (i >= NREL * NEDGES) return;
    int r = i / NEDGES;
    int d = dst[i];
    int pos = atomicAdd(&cursor[r * NNODES + d], 1);
    lists[(size_t)r * NEDGES + off[r * NNODES + d] + pos] = src[i];
}

// ---------------------------------------------------------------------------
// prep: weight sum + bf16 split
// ---------------------------------------------------------------------------
__global__ void k_sumw(const float* __restrict__ W, float* __restrict__ out, int sz) {
    int i = blockIdx.x * blockDim.x + threadIdx.x;
    if (i >= sz) return;
    float s = 0.0f;
#pragma unroll
    for (int r = 0; r < NREL; r++) s += W[(size_t)r * sz + i];
    out[i] = s;
}

__global__ void k_split(const float* __restrict__ in, bf16* __restrict__ hi,
                        bf16* __restrict__ lo, size_t n, int relu) {
    size_t i = (size_t)blockIdx.x * blockDim.x + threadIdx.x;
    if (i >= n) return;
    float v = in[i];
    if (relu) v = fmaxf(v, 0.0f);
    bf16 h = __float2bfloat16(v);
    hi[i] = h;
    lo[i] = __float2bfloat16(v - __bfloat162float(h));
}

// ---------------------------------------------------------------------------
// bf16x3 tensor-core GEMM (z-batched): for z in grid.z:
//   C_z[M,N] = (Ahi+Alo)[M,K] @ (Bhi+Blo)_z[K,N] (+bias)
// B_z = B + z*wstride, C_z = C + z*cplane
// ---------------------------------------------------------------------------
#define GBM 128
#define GBN 128
#define GBK 32
#define SA_STRIDE 40
#define SB_STRIDE 136
#define SA_BYTES (2 * 2 * 128 * SA_STRIDE * 2)
#define SB_BYTES (2 * 2 * 32 * SB_STRIDE * 2)
#define GEMM_SMEM (SA_BYTES + SB_BYTES)

__device__ __forceinline__ void cp16(uint32_t dst, const void* src, bool pred) {
    int sz = pred ? 16 : 0;
    asm volatile("cp.async.cg.shared.global [%0], [%1], 16, %2;"
                 :: "r"(dst), "l"(src), "r"(sz));
}
__device__ __forceinline__ void ldsm_x4(uint32_t* r, uint32_t addr) {
    asm volatile("ldmatrix.sync.aligned.m8n8.x4.shared.b16 {%0,%1,%2,%3}, [%4];"
                 : "=r"(r[0]), "=r"(r[1]), "=r"(r[2]), "=r"(r[3]) : "r"(addr));
}
__device__ __forceinline__ void ldsm_x4t(uint32_t* r, uint32_t addr) {
    asm volatile("ldmatrix.sync.aligned.m8n8.x4.trans.shared.b16 {%0,%1,%2,%3}, [%4];"
                 : "=r"(r[0]), "=r"(r[1]), "=r"(r[2]), "=r"(r[3]) : "r"(addr));
}
__device__ __forceinline__ void mma_bf16(float* c, const uint32_t* a, const uint32_t* b) {
    asm volatile(
        "mma.sync.aligned.m16n8k16.row.col.f32.bf16.bf16.f32 "
        "{%0,%1,%2,%3}, {%4,%5,%6,%7}, {%8,%9}, {%0,%1,%2,%3};"
        : "+f"(c[0]), "+f"(c[1]), "+f"(c[2]), "+f"(c[3])
        : "r"(a[0]), "r"(a[1]), "r"(a[2]), "r"(a[3]), "r"(b[0]), "r"(b[1]));
}

template <int HAS_BIAS>
__global__ void __launch_bounds__(256, 1) k_mma(
    const bf16* __restrict__ Ahi, const bf16* __restrict__ Alo,
    const bf16* __restrict__ Bhi_base, const bf16* __restrict__ Blo_base,
    float* __restrict__ C_base, const float* __restrict__ bias,
    int M, int N, int K, size_t wstride, size_t cplane)
{
    extern __shared__ __align__(16) char smem_raw[];
    bf16* sA = (bf16*)smem_raw;
    bf16* sB = (bf16*)(smem_raw + SA_BYTES);

    const int tid  = threadIdx.x;
    const int lane = tid & 31;
    const int warp = tid >> 5;
    const int bm   = blockIdx.y * GBM;
    const int bn   = blockIdx.x * GBN;
    const int m_base = (warp & 1) * 64;
    const int n_base = (warp >> 1) * 32;

    const bf16* Bhi = Bhi_base + (size_t)blockIdx.z * wstride;
    const bf16* Blo = Blo_base + (size_t)blockIdx.z * wstride;
    float* C = C_base + (size_t)blockIdx.z * cplane;

    const uint32_t sA_u = (uint32_t)__cvta_generic_to_shared(sA);
    const uint32_t sB_u = (uint32_t)__cvta_generic_to_shared(sB);

    const bf16* Ag[2] = {Ahi, Alo};
    const bf16* Bg[2] = {Bhi, Blo};

    auto load_tile = [&](int kt, int stage) {
        const int k0 = kt * GBK;
#pragma unroll
        for (int h = 0; h < 2; h++) {
#pragma unroll
            for (int i = 0; i < 2; i++) {
                int c = tid + i * 256;
                int row = c >> 2, col = (c & 3) * 8;
                int rg = bm + row;
                bool ok = rg < M;
                int rc = ok ? rg : (M - 1);
                uint32_t dst = sA_u + (((stage * 2 + h) * 128 + row) * SA_STRIDE + col) * 2;
                cp16(dst, Ag[h] + (size_t)rc * K + k0 + col, ok);
            }
        }
#pragma unroll
        for (int h = 0; h < 2; h++) {
#pragma unroll
            for (int i = 0; i < 2; i++) {
                int c = tid + i * 256;
                int row = c >> 4, col = (c & 15) * 8;
                uint32_t dst = sB_u + (((stage * 2 + h) * 32 + row) * SB_STRIDE + col) * 2;
                cp16(dst, Bg[h] + (size_t)(k0 + row) * N + bn + col, true);
            }
        }
    };

    float acc[4][4][4];
#pragma unroll
    for (int i = 0; i < 4; i++)
#pragma unroll
        for (int j = 0; j < 4; j++)
#pragma unroll
            for (int k = 0; k < 4; k++) acc[i][j][k] = 0.0f;

    const int KT = K >> 5;

    load_tile(0, 0);
    asm volatile("cp.async.commit_group;");

    for (int kt = 0; kt < KT; kt++) {
        const int stage = kt & 1;
        if (kt + 1 < KT) {
            load_tile(kt + 1, (kt + 1) & 1);
            asm volatile("cp.async.commit_group;");
            asm volatile("cp.async.wait_group 1;");
        } else {
            asm volatile("cp.async.wait_group 0;");
        }
        __syncthreads();

#pragma unroll
        for (int ks = 0; ks < 2; ks++) {
            const int k0s = ks * 16;
            uint32_t afr[2][4][4];
#pragma unroll
            for (int h = 0; h < 2; h++)
#pragma unroll
                for (int am = 0; am < 4; am++) {
                    int row = m_base + am * 16 + (lane & 15);
                    int col = k0s + 8 * (lane >> 4);
                    uint32_t addr = sA_u + (((stage * 2 + h) * 128 + row) * SA_STRIDE + col) * 2;
                    ldsm_x4(afr[h][am], addr);
                }
            uint32_t bfr[2][4][2];
#pragma unroll
            for (int h = 0; h < 2; h++)
#pragma unroll
                for (int bp = 0; bp < 2; bp++) {
                    int row = k0s + (lane & 15);
                    int col = n_base + bp * 16 + 8 * (lane >> 4);
                    uint32_t addr = sB_u + (((stage * 2 + h) * 32 + row) * SB_STRIDE + col) * 2;
                    uint32_t r[4];
                    ldsm_x4t(r, addr);
                    bfr[h][bp * 2][0] = r[0]; bfr[h][bp * 2][1] = r[1];
                    bfr[h][bp * 2 + 1][0] = r[2]; bfr[h][bp * 2 + 1][1] = r[3];
                }
#pragma unroll
            for (int am = 0; am < 4; am++)
#pragma unroll
                for (int an = 0; an < 4; an++) {
                    mma_bf16(acc[am][an], afr[0][am], bfr[0][an]);
                    mma_bf16(acc[am][an], afr[0][am], bfr[1][an]);
                    mma_bf16(acc[am][an], afr[1][am], bfr[0][an]);
                }
        }
        __syncthreads();
    }

#pragma unroll
    for (int am = 0; am < 4; am++) {
#pragma unroll
        for (int an = 0; an < 4; an++) {
            int col = bn + n_base + an * 8 + (lane & 3) * 2;
            float bx = 0.f, by = 0.f;
            if (HAS_BIAS) { bx = bias[col]; by = bias[col + 1]; }
            int row0 = bm + m_base + am * 16 + (lane >> 2);
            if (row0 < M) {
                float2 v = make_float2(acc[am][an][0] + bx, acc[am][an][1] + by);
                *(float2*)&C[(size_t)row0 * N + col] = v;
            }
            int row1 = row0 + 8;
            if (row1 < M) {
                float2 v = make_float2(acc[am][an][2] + bx, acc[am][an][3] + by);
                *(float2*)&C[(size_t)row1 * N + col] = v;
            }
        }
    }
}

// ---------------------------------------------------------------------------
// CSR gather: out[d,:] += sum_r invdeg_r(d) * sum_{s in lists_r(d)} Y_r[s,:]
// block = one dst node, blockDim = F/4 threads, float4 per thread
// ---------------------------------------------------------------------------
template <int F>
__global__ void k_gather(const float* __restrict__ Y, size_t plane,
                         const int* __restrict__ off, const int* __restrict__ deg,
                         const int* __restrict__ lists, float* __restrict__ out)
{
    const int d = blockIdx.x;
    const int t = threadIdx.x;
    float4 acc = make_float4(0.f, 0.f, 0.f, 0.f);

#pragma unroll
    for (int r = 0; r < NREL; r++) {
        int o  = off[r * NNODES + d];
        int dg = deg[r * NNODES + d];
        if (dg == 0) continue;
        float w = 1.0f / (float)dg;
        const int* lp = lists + (size_t)r * NEDGES + o;
        const float* Yp = Y + r * plane;
        float4 tmp = make_float4(0.f, 0.f, 0.f, 0.f);
        for (int k = 0; k < dg; k++) {
            int s = lp[k];
            float4 v = *(const float4*)(Yp + (size_t)s * F + t * 4);
            tmp.x += v.x; tmp.y += v.y; tmp.z += v.z; tmp.w += v.w;
        }
        acc.x += w * tmp.x; acc.y += w * tmp.y;
        acc.z += w * tmp.z; acc.w += w * tmp.w;
    }

    float4 o4 = *(float4*)(out + (size_t)d * F + t * 4);
    o4.x += acc.x; o4.y += acc.y; o4.z += acc.z; o4.w += acc.w;
    *(float4*)(out + (size_t)d * F + t * 4) = o4;
}

// ---------------------------------------------------------------------------
// launch
// ---------------------------------------------------------------------------
extern "C" void kernel_launch(void* const* d_in, const int* in_sizes, int n_in,
                              void* d_out, int out_size)
{
    const float* x       = (const float*)d_in[0];
    const float* Wself1  = (const float*)d_in[1];
    const float* Wneigh1 = (const float*)d_in[2];
    const float* b1      = (const float*)d_in[3];
    const float* Wself2  = (const float*)d_in[4];
    const float* Wneigh2 = (const float*)d_in[5];
    const float* b2      = (const float*)d_in[6];
    const void*  esrc    = d_in[7];
    const void*  edst    = d_in[8];
    float*       out     = (float*)d_out;

    float *H1, *Y, *Ws1, *bs1, *Ws2, *bs2;
    int *src32, *dst32, *deg, *off, *cursor, *bsum, *lists;
    bf16 *Xhi, *Xlo, *Hhi, *Hlo, *Whi, *Wlo;
    cudaGetSymbolAddress((void**)&H1,     g_H1);
    cudaGetSymbolAddress((void**)&Y,      g_Y);
    cudaGetSymbolAddress((void**)&Ws1,    g_Ws1);
    cudaGetSymbolAddress((void**)&bs1,    g_bs1);
    cudaGetSymbolAddress((void**)&Ws2,    g_Ws2);
    cudaGetSymbolAddress((void**)&bs2,    g_bs2);
    cudaGetSymbolAddress((void**)&src32,  g_src32);
    cudaGetSymbolAddress((void**)&dst32,  g_dst32);
    cudaGetSymbolAddress((void**)&deg,    g_deg);
    cudaGetSymbolAddress((void**)&off,    g_off);
    cudaGetSymbolAddress((void**)&cursor, g_cursor);
    cudaGetSymbolAddress((void**)&bsum,   g_bsum);
    cudaGetSymbolAddress((void**)&lists,  g_lists);
    cudaGetSymbolAddress((void**)&Xhi,    g_Xhi);
    cudaGetSymbolAddress((void**)&Xlo,    g_Xlo);
    cudaGetSymbolAddress((void**)&Hhi,    g_Hhi);
    cudaGetSymbolAddress((void**)&Hlo,    g_Hlo);
    cudaGetSymbolAddress((void**)&Whi,    g_Whi);
    cudaGetSymbolAddress((void**)&Wlo,    g_Wlo);

    static bool attr_done = false;
    if (!attr_done) {
        cudaFuncSetAttribute(k_mma<0>, cudaFuncAttributeMaxDynamicSharedMemorySize, GEMM_SMEM);
        cudaFuncSetAttribute(k_mma<1>, cudaFuncAttributeMaxDynamicSharedMemorySize, GEMM_SMEM);
        attr_done = true;
    }

    const int T = 256;
    const int NE = NREL * NEDGES;
    const size_t YPLANE = (size_t)NNODES * HIDF;   // per-relation Y plane stride

    // edge dtype detect + convert (both arrays in one kernel)
    k_detect<<<1, 32>>>((const unsigned*)esrc);
    k_cvt2<<<(NE + T - 1) / T, T>>>(esrc, src32, edst, dst32, NE);

    // CSR build
    k_zeroi<<<(2 * NREL * NNODES + T - 1) / T, T>>>(deg, 2 * NREL * NNODES);  // deg+off contiguous? no: zero separately
    k_zeroi<<<(NREL * NNODES + T - 1) / T, T>>>(cursor, NREL * NNODES);
    k_degcount<<<(NE + T - 1) / T, T>>>(dst32, deg);
    k_scanA<<<NREL * NCHUNK, 1024>>>(deg, off, bsum);
    k_scanB<<<1, 32>>>(bsum);
    k_scanC<<<NREL * NCHUNK, 1024>>>(off, bsum);
    k_fill<<<(NE + T - 1) / T, T>>>(src32, dst32, off, cursor, lists);

    // summed self-weights / biases, then bf16 hi/lo splits
    k_sumw<<<(W_L1_SZ + T - 1) / T, T>>>(Wself1, Ws1, W_L1_SZ);
    k_sumw<<<(HIDF + T - 1) / T, T>>>(b1, bs1, HIDF);
    k_sumw<<<(W_L2_SZ + T - 1) / T, T>>>(Wself2, Ws2, W_L2_SZ);
    k_sumw<<<(OUTF + T - 1) / T, T>>>(b2, bs2, OUTF);

    k_split<<<(W_L1_SZ + T - 1) / T, T>>>(Ws1, Whi, Wlo, W_L1_SZ, 0);
    k_split<<<(NREL * W_L1_SZ + T - 1) / T, T>>>(Wneigh1, Whi + W_L1_SZ, Wlo + W_L1_SZ,
                                                 (size_t)NREL * W_L1_SZ, 0);
    k_split<<<(W_L2_SZ + T - 1) / T, T>>>(Ws2, Whi + W_L2_OFF, Wlo + W_L2_OFF, W_L2_SZ, 0);
    k_split<<<(NREL * W_L2_SZ + T - 1) / T, T>>>(Wneigh2, Whi + W_L2_OFF + W_L2_SZ,
                                                 Wlo + W_L2_OFF + W_L2_SZ,
                                                 (size_t)NREL * W_L2_SZ, 0);
    {
        size_t n = (size_t)NNODES * INF;
        k_split<<<(unsigned)((n + T - 1) / T), T>>>(x, Xhi, Xlo, n, 0);
    }

    const int MB = (NNODES + GBM - 1) / GBM;

    // -------- layer 1 --------
    {
        dim3 gs(HIDF / GBN, MB, 1);
        k_mma<1><<<gs, T, GEMM_SMEM>>>(Xhi, Xlo, Whi, Wlo, H1, bs1,
                                       NNODES, HIDF, INF, 0, 0);
        dim3 gn(HIDF / GBN, MB, NREL);
        k_mma<0><<<gn, T, GEMM_SMEM>>>(Xhi, Xlo, Whi + W_L1_SZ, Wlo + W_L1_SZ, Y, nullptr,
                                       NNODES, HIDF, INF, W_L1_SZ, YPLANE);
        k_gather<HIDF><<<NNODES, HIDF / 4>>>(Y, YPLANE, off, deg, lists, H1);
    }

    // relu + split H1
    {
        size_t n = (size_t)NNODES * HIDF;
        k_split<<<(unsigned)((n + T - 1) / T), T>>>(H1, Hhi, Hlo, n, 1);
    }

    // -------- layer 2 --------
    {
        dim3 gs(OUTF / GBN, MB, 1);
        k_mma<1><<<gs, T, GEMM_SMEM>>>(Hhi, Hlo, Whi + W_L2_OFF, Wlo + W_L2_OFF, out, bs2,
                                       NNODES, OUTF, HIDF, 0, 0);
        dim3 gn(OUTF / GBN, MB, NREL);
        k_mma<0><<<gn, T, GEMM_SMEM>>>(Hhi, Hlo, Whi + W_L2_OFF + W_L2_SZ,
                                       Wlo + W_L2_OFF + W_L2_SZ, Y, nullptr,
                                       NNODES, OUTF, HIDF, W_L2_SZ, YPLANE);
        k_gather<OUTF><<<NNODES, OUTF / 4>>>(Y, YPLANE, off, deg, lists, out);
    }
}

// round 6
// speedup vs baseline: 2.9824x; 1.0191x over previous
#include <cuda_runtime.h>
#include <cuda_bf16.h>
#include <cstdint>

// Problem constants (fixed by the reference)
#define NNODES 50000
#define NREL   4
#define NEDGES 250000
#define INF    512
#define HIDF   512
#define OUTF   256

#define NCHUNK 49          // ceil(50000/1024)
typedef __nv_bfloat16 bf16;

#define W_L1_SZ (512 * 512)
#define W_L2_SZ (512 * 256)
#define W_L2_OFF (5 * W_L1_SZ)
#define W_TOT (5 * W_L1_SZ + 5 * W_L2_SZ)

// -------- scratch (device globals: no allocation in kernel_launch) --------
__device__ __align__(16) float g_Y [(size_t)5 * NNODES * HIDF];  // 5 planes (self + 4 rel)
__device__ __align__(16) float g_bs1[HIDF];
__device__ __align__(16) float g_bs2[OUTF];
__device__ __align__(16) int   g_src32[NREL * NEDGES];
__device__ __align__(16) int   g_dst32[NREL * NEDGES];
__device__ __align__(16) int   g_deg[NREL * NNODES];
__device__ __align__(16) int   g_off[NREL * NNODES];
__device__ __align__(16) int   g_cursor[NREL * NNODES];
__device__ __align__(16) int   g_bsum[NREL * NCHUNK];
__device__ __align__(16) int   g_lists[NREL * NEDGES];
__device__ int g_is64;

__device__ __align__(16) bf16 g_Xhi[(size_t)NNODES * INF];
__device__ __align__(16) bf16 g_Xlo[(size_t)NNODES * INF];
__device__ __align__(16) bf16 g_Hhi[(size_t)NNODES * HIDF];
__device__ __align__(16) bf16 g_Hlo[(size_t)NNODES * HIDF];
__device__ __align__(16) bf16 g_Whi[W_TOT];
__device__ __align__(16) bf16 g_Wlo[W_TOT];

// ---------------------------------------------------------------------------
// edge dtype detection + conversion
// ---------------------------------------------------------------------------
__global__ void k_detect(const unsigned* __restrict__ w) {
    if (threadIdx.x == 0 && blockIdx.x == 0) {
        unsigned acc = 0;
        for (int i = 0; i < 64; i++) acc |= w[2 * i + 1];
        g_is64 = (acc == 0) ? 1 : 0;
    }
}

__global__ void k_cvt2(const void* __restrict__ ps, int* __restrict__ os,
                       const void* __restrict__ pd, int* __restrict__ od, int n) {
    int i = blockIdx.x * blockDim.x + threadIdx.x;
    if (i >= n) return;
    if (g_is64) {
        os[i] = (int)((const long long*)ps)[i];
        od[i] = (int)((const long long*)pd)[i];
    } else {
        os[i] = ((const int*)ps)[i];
        od[i] = ((const int*)pd)[i];
    }
}

// ---------------------------------------------------------------------------
// prep: X split; weight sum+split (plane0 = sum self, planes 1..4 = neigh r)
// ---------------------------------------------------------------------------
__global__ void k_split(const float* __restrict__ in, bf16* __restrict__ hi,
                        bf16* __restrict__ lo, size_t n) {
    size_t i = (size_t)blockIdx.x * blockDim.x + threadIdx.x;
    if (i >= n) return;
    float v = in[i];
    bf16 h = __float2bfloat16(v);
    hi[i] = h;
    lo[i] = __float2bfloat16(v - __bfloat162float(h));
}

__global__ void k_sumsplit(const float* __restrict__ Wself,
                           const float* __restrict__ Wneigh,
                           const float* __restrict__ b,
                           bf16* __restrict__ whi, bf16* __restrict__ wlo,
                           float* __restrict__ bias_out, int sz, int nf) {
    int i = blockIdx.x * blockDim.x + threadIdx.x;
    if (i >= sz) return;
    float s = 0.0f;
#pragma unroll
    for (int r = 0; r < NREL; r++) s += Wself[(size_t)r * sz + i];
    bf16 h = __float2bfloat16(s);
    whi[i] = h;
    wlo[i] = __float2bfloat16(s - __bfloat162float(h));
#pragma unroll
    for (int r = 0; r < NREL; r++) {
        float v = Wneigh[(size_t)r * sz + i];
        bf16 hh = __float2bfloat16(v);
        whi[(size_t)(1 + r) * sz + i] = hh;
        wlo[(size_t)(1 + r) * sz + i] = __float2bfloat16(v - __bfloat162float(hh));
    }
    if (i < nf) {
        float bb = 0.0f;
#pragma unroll
        for (int r = 0; r < NREL; r++) bb += b[r * nf + i];
        bias_out[i] = bb;
    }
}

// ---------------------------------------------------------------------------
// CSR build
// ---------------------------------------------------------------------------
__global__ void k_zeroi(int* __restrict__ p, int n) {
    int i = blockIdx.x * blockDim.x + threadIdx.x;
    if (i < n) p[i] = 0;
}

__global__ void k_degcount(const int* __restrict__ dst, int* __restrict__ deg) {
    int i = blockIdx.x * blockDim.x + threadIdx.x;
    if (i >= NREL * NEDGES) return;
    int r = i / NEDGES;
    atomicAdd(&deg[r * NNODES + dst[i]], 1);
}

__global__ void k_scanA(const int* __restrict__ deg, int* __restrict__ off,
                        int* __restrict__ bsum) {
    __shared__ int s[1024];
    int r = blockIdx.x / NCHUNK;
    int c = blockIdx.x % NCHUNK;
    int idx = c * 1024 + threadIdx.x;
    int v = (idx < NNODES) ? deg[r * NNODES + idx] : 0;
    s[threadIdx.x] = v;
    __syncthreads();
#pragma unroll
    for (int d = 1; d < 1024; d <<= 1) {
        int t = (threadIdx.x >= d) ? s[threadIdx.x - d] : 0;
        __syncthreads();
        s[threadIdx.x] += t;
        __syncthreads();
    }
    if (idx < NNODES) off[r * NNODES + idx] = s[threadIdx.x] - v;
    if (threadIdx.x == 1023) bsum[r * NCHUNK + c] = s[1023];
}

__global__ void k_scanB(int* __restrict__ bsum) {
    int r = threadIdx.x;
    if (r >= NREL) return;
    int run = 0;
    for (int c = 0; c < NCHUNK; c++) {
        int v = bsum[r * NCHUNK + c];
        bsum[r * NCHUNK + c] = run;
        run += v;
    }
}

__global__ void k_scanC(int* __restrict__ off, const int* __restrict__ bsum) {
    int r = blockIdx.x / NCHUNK;
    int c = blockIdx.x % NCHUNK;
    int idx = c * 1024 + threadIdx.x;
    if (idx < NNODES) off[r * NNODES + idx] += bsum[r * NCHUNK + c];
}

__global__ void k_fill(const int* __restrict__ src, const int* __restrict__ dst,
                       const int* __restrict__ off, int* __restrict__ cursor,
                       int* __restrict__ lists) {
    int i = blockIdx.x * blockDim.x + threadIdx.x;
    if (i >= NREL * NEDGES) return;
    int r = i / NEDGES;
    int d = dst[i];
    int pos = atomicAdd(&cursor[r * NNODES + d], 1);
    lists[(size_t)r * NEDGES + off[r * NNODES + d] + pos] = src[i];
}

// ---------------------------------------------------------------------------
// bf16x3 tensor-core GEMM, z-batched over 5 weight planes, 3-stage cp.async
//   C_z[M,N] = (Ahi+Alo)[M,K] @ (Whi+Wlo)_z[K,N]  (+bias on z==0)
// ---------------------------------------------------------------------------
#define GBM 128
#define GBN 128
#define GBK 32
#define SA_STRIDE 40
#define SB_STRIDE 136
#define SA_STAGE (2 * 128 * SA_STRIDE * 2)   // 20480 B
#define SB_STAGE (2 * 32 * SB_STRIDE * 2)    // 17408 B
#define NSTAGE 3
#define SA_BYTES (NSTAGE * SA_STAGE)
#define GEMM_SMEM (NSTAGE * (SA_STAGE + SB_STAGE))   // 113664

__device__ __forceinline__ void cp16(uint32_t dst, const void* src, bool pred) {
    int sz = pred ? 16 : 0;
    asm volatile("cp.async.cg.shared.global [%0], [%1], 16, %2;"
                 :: "r"(dst), "l"(src), "r"(sz));
}
__device__ __forceinline__ void ldsm_x4(uint32_t* r, uint32_t addr) {
    asm volatile("ldmatrix.sync.aligned.m8n8.x4.shared.b16 {%0,%1,%2,%3}, [%4];"
                 : "=r"(r[0]), "=r"(r[1]), "=r"(r[2]), "=r"(r[3]) : "r"(addr));
}
__device__ __forceinline__ void ldsm_x4t(uint32_t* r, uint32_t addr) {
    asm volatile("ldmatrix.sync.aligned.m8n8.x4.trans.shared.b16 {%0,%1,%2,%3}, [%4];"
                 : "=r"(r[0]), "=r"(r[1]), "=r"(r[2]), "=r"(r[3]) : "r"(addr));
}
__device__ __forceinline__ void mma_bf16(float* c, const uint32_t* a, const uint32_t* b) {
    asm volatile(
        "mma.sync.aligned.m16n8k16.row.col.f32.bf16.bf16.f32 "
        "{%0,%1,%2,%3}, {%4,%5,%6,%7}, {%8,%9}, {%0,%1,%2,%3};"
        : "+f"(c[0]), "+f"(c[1]), "+f"(c[2]), "+f"(c[3])
        : "r"(a[0]), "r"(a[1]), "r"(a[2]), "r"(a[3]), "r"(b[0]), "r"(b[1]));
}

__global__ void __launch_bounds__(256, 1) k_mma(
    const bf16* __restrict__ Ahi, const bf16* __restrict__ Alo,
    const bf16* __restrict__ Whi_base, const bf16* __restrict__ Wlo_base,
    float* __restrict__ C_base, const float* __restrict__ bias,
    int M, int N, int K, size_t wstride, size_t cplane)
{
    extern __shared__ __align__(16) char smem_raw[];
    const int tid  = threadIdx.x;
    const int lane = tid & 31;
    const int warp = tid >> 5;
    const int bm   = blockIdx.y * GBM;
    const int bn   = blockIdx.x * GBN;
    const int m_base = (warp & 1) * 64;
    const int n_base = (warp >> 1) * 32;

    const bf16* Bhi = Whi_base + (size_t)blockIdx.z * wstride;
    const bf16* Blo = Wlo_base + (size_t)blockIdx.z * wstride;
    float* C = C_base + (size_t)blockIdx.z * cplane;

    const uint32_t sA_u = (uint32_t)__cvta_generic_to_shared(smem_raw);
    const uint32_t sB_u = (uint32_t)__cvta_generic_to_shared(smem_raw + SA_BYTES);

    const bf16* Ag[2] = {Ahi, Alo};
    const bf16* Bg[2] = {Bhi, Blo};

    auto load_tile = [&](int kt, int st) {
        const int k0 = kt * GBK;
#pragma unroll
        for (int h = 0; h < 2; h++) {
#pragma unroll
            for (int i = 0; i < 2; i++) {
                int c = tid + i * 256;
                int row = c >> 2, col = (c & 3) * 8;
                int rg = bm + row;
                bool ok = rg < M;
                int rc = ok ? rg : (M - 1);
                uint32_t dst = sA_u + st * SA_STAGE + ((h * 128 + row) * SA_STRIDE + col) * 2;
                cp16(dst, Ag[h] + (size_t)rc * K + k0 + col, ok);
            }
        }
#pragma unroll
        for (int h = 0; h < 2; h++) {
#pragma unroll
            for (int i = 0; i < 2; i++) {
                int c = tid + i * 256;
                int row = c >> 4, col = (c & 15) * 8;
                uint32_t dst = sB_u + st * SB_STAGE + ((h * 32 + row) * SB_STRIDE + col) * 2;
                cp16(dst, Bg[h] + (size_t)(k0 + row) * N + bn + col, true);
            }
        }
    };

    float acc[4][4][4];
#pragma unroll
    for (int i = 0; i < 4; i++)
#pragma unroll
        for (int j = 0; j < 4; j++)
#pragma unroll
            for (int k = 0; k < 4; k++) acc[i][j][k] = 0.0f;

    const int KT = K >> 5;

    load_tile(0, 0);
    asm volatile("cp.async.commit_group;");
    load_tile(1, 1);
    asm volatile("cp.async.commit_group;");

    for (int kt = 0; kt < KT; kt++) {
        const int st = kt % NSTAGE;
        if (kt + 2 < KT) load_tile(kt + 2, (kt + 2) % NSTAGE);
        asm volatile("cp.async.commit_group;");
        asm volatile("cp.async.wait_group 2;");
        __syncthreads();

#pragma unroll
        for (int ks = 0; ks < 2; ks++) {
            const int k0s = ks * 16;
            uint32_t afr[2][4][4];
#pragma unroll
            for (int h = 0; h < 2; h++)
#pragma unroll
                for (int am = 0; am < 4; am++) {
                    int row = m_base + am * 16 + (lane & 15);
                    int col = k0s + 8 * (lane >> 4);
                    uint32_t addr = sA_u + st * SA_STAGE + ((h * 128 + row) * SA_STRIDE + col) * 2;
                    ldsm_x4(afr[h][am], addr);
                }
            uint32_t bfr[2][4][2];
#pragma unroll
            for (int h = 0; h < 2; h++)
#pragma unroll
                for (int bp = 0; bp < 2; bp++) {
                    int row = k0s + (lane & 15);
                    int col = n_base + bp * 16 + 8 * (lane >> 4);
                    uint32_t addr = sB_u + st * SB_STAGE + ((h * 32 + row) * SB_STRIDE + col) * 2;
                    uint32_t r[4];
                    ldsm_x4t(r, addr);
                    bfr[h][bp * 2][0] = r[0]; bfr[h][bp * 2][1] = r[1];
                    bfr[h][bp * 2 + 1][0] = r[2]; bfr[h][bp * 2 + 1][1] = r[3];
                }
#pragma unroll
            for (int am = 0; am < 4; am++)
#pragma unroll
                for (int an = 0; an < 4; an++) {
                    mma_bf16(acc[am][an], afr[0][am], bfr[0][an]);
                    mma_bf16(acc[am][an], afr[0][am], bfr[1][an]);
                    mma_bf16(acc[am][an], afr[1][am], bfr[0][an]);
                }
        }
        __syncthreads();
    }

    const bool do_bias = (bias != nullptr) && (blockIdx.z == 0);
#pragma unroll
    for (int am = 0; am < 4; am++) {
#pragma unroll
        for (int an = 0; an < 4; an++) {
            int col = bn + n_base + an * 8 + (lane & 3) * 2;
            float bx = 0.f, by = 0.f;
            if (do_bias) { bx = bias[col]; by = bias[col + 1]; }
            int row0 = bm + m_base + am * 16 + (lane >> 2);
            if (row0 < M) {
                float2 v = make_float2(acc[am][an][0] + bx, acc[am][an][1] + by);
                *(float2*)&C[(size_t)row0 * N + col] = v;
            }
            int row1 = row0 + 8;
            if (row1 < M) {
                float2 v = make_float2(acc[am][an][2] + bx, acc[am][an][3] + by);
                *(float2*)&C[(size_t)row1 * N + col] = v;
            }
        }
    }
}

// ---------------------------------------------------------------------------
// gather1: H = relu(plane0 + sum_r invdeg*sum Y_{1+r}[src]) -> bf16 hi/lo split
// block = dst node, 128 threads, float4/thread
// ---------------------------------------------------------------------------
__global__ void k_gather1(const float* __restrict__ Y,
                          const int* __restrict__ off, const int* __restrict__ deg,
                          const int* __restrict__ lists,
                          bf16* __restrict__ Hhi, bf16* __restrict__ Hlo)
{
    const int d = blockIdx.x;
    const int t = threadIdx.x;
    const size_t plane = (size_t)NNODES * HIDF;

    float4 acc = *(const float4*)(Y + (size_t)d * HIDF + t * 4);   // self + bias

#pragma unroll
    for (int r = 0; r < NREL; r++) {
        int dg = deg[r * NNODES + d];
        if (dg == 0) continue;
        int o = off[r * NNODES + d];
        float w = 1.0f / (float)dg;
        const int* lp = lists + (size_t)r * NEDGES + o;
        const float* Yp = Y + (size_t)(1 + r) * plane;
        float4 tmp = make_float4(0.f, 0.f, 0.f, 0.f);
        for (int k = 0; k < dg; k++) {
            int s = lp[k];
            float4 v = *(const float4*)(Yp + (size_t)s * HIDF + t * 4);
            tmp.x += v.x; tmp.y += v.y; tmp.z += v.z; tmp.w += v.w;
        }
        acc.x += w * tmp.x; acc.y += w * tmp.y;
        acc.z += w * tmp.z; acc.w += w * tmp.w;
    }

    // relu + bf16 hi/lo split
    float vv[4] = {fmaxf(acc.x, 0.f), fmaxf(acc.y, 0.f),
                   fmaxf(acc.z, 0.f), fmaxf(acc.w, 0.f)};
    size_t base = (size_t)d * HIDF + t * 4;
    bf16 hi4[4], lo4[4];
#pragma unroll
    for (int j = 0; j < 4; j++) {
        bf16 h = __float2bfloat16(vv[j]);
        hi4[j] = h;
        lo4[j] = __float2bfloat16(vv[j] - __bfloat162float(h));
    }
    *(uint2*)(Hhi + base) = *(uint2*)hi4;
    *(uint2*)(Hlo + base) = *(uint2*)lo4;
}

// gather2: out = plane0 + sum_r invdeg*sum Y_{1+r}[src]  (OUTF wide, 64 threads)
__global__ void k_gather2(const float* __restrict__ Y,
                          const int* __restrict__ off, const int* __restrict__ deg,
                          const int* __restrict__ lists, float* __restrict__ out)
{
    const int d = blockIdx.x;
    const int t = threadIdx.x;
    const size_t plane = (size_t)NNODES * OUTF;

    float4 acc = *(const float4*)(Y + (size_t)d * OUTF + t * 4);

#pragma unroll
    for (int r = 0; r < NREL; r++) {
        int dg = deg[r * NNODES + d];
        if (dg == 0) continue;
        int o = off[r * NNODES + d];
        float w = 1.0f / (float)dg;
        const int* lp = lists + (size_t)r * NEDGES + o;
        const float* Yp = Y + (size_t)(1 + r) * plane;
        float4 tmp = make_float4(0.f, 0.f, 0.f, 0.f);
        for (int k = 0; k < dg; k++) {
            int s = lp[k];
            float4 v = *(const float4*)(Yp + (size_t)s * OUTF + t * 4);
            tmp.x += v.x; tmp.y += v.y; tmp.z += v.z; tmp.w += v.w;
        }
        acc.x += w * tmp.x; acc.y += w * tmp.y;
        acc.z += w * tmp.z; acc.w += w * tmp.w;
    }

    *(float4*)(out + (size_t)d * OUTF + t * 4) = acc;
}

// ---------------------------------------------------------------------------
// launch
// ---------------------------------------------------------------------------
extern "C" void kernel_launch(void* const* d_in, const int* in_sizes, int n_in,
                              void* d_out, int out_size)
{
    const float* x       = (const float*)d_in[0];
    const float* Wself1  = (const float*)d_in[1];
    const float* Wneigh1 = (const float*)d_in[2];
    const float* b1      = (const float*)d_in[3];
    const float* Wself2  = (const float*)d_in[4];
    const float* Wneigh2 = (const float*)d_in[5];
    const float* b2      = (const float*)d_in[6];
    const void*  esrc    = d_in[7];
    const void*  edst    = d_in[8];
    float*       out     = (float*)d_out;

    float *Y, *bs1, *bs2;
    int *src32, *dst32, *deg, *off, *cursor, *bsum, *lists;
    bf16 *Xhi, *Xlo, *Hhi, *Hlo, *Whi, *Wlo;
    cudaGetSymbolAddress((void**)&Y,      g_Y);
    cudaGetSymbolAddress((void**)&bs1,    g_bs1);
    cudaGetSymbolAddress((void**)&bs2,    g_bs2);
    cudaGetSymbolAddress((void**)&src32,  g_src32);
    cudaGetSymbolAddress((void**)&dst32,  g_dst32);
    cudaGetSymbolAddress((void**)&deg,    g_deg);
    cudaGetSymbolAddress((void**)&off,    g_off);
    cudaGetSymbolAddress((void**)&cursor, g_cursor);
    cudaGetSymbolAddress((void**)&bsum,   g_bsum);
    cudaGetSymbolAddress((void**)&lists,  g_lists);
    cudaGetSymbolAddress((void**)&Xhi,    g_Xhi);
    cudaGetSymbolAddress((void**)&Xlo,    g_Xlo);
    cudaGetSymbolAddress((void**)&Hhi,    g_Hhi);
    cudaGetSymbolAddress((void**)&Hlo,    g_Hlo);
    cudaGetSymbolAddress((void**)&Whi,    g_Whi);
    cudaGetSymbolAddress((void**)&Wlo,    g_Wlo);

    static bool attr_done = false;
    if (!attr_done) {
        cudaFuncSetAttribute(k_mma, cudaFuncAttributeMaxDynamicSharedMemorySize, GEMM_SMEM);
        attr_done = true;
    }

    const int T = 256;
    const int NE = NREL * NEDGES;
    const size_t PL1 = (size_t)NNODES * HIDF;
    const size_t PL2 = (size_t)NNODES * OUTF;
    const int MB = (NNODES + GBM - 1) / GBM;

    // 1-5: prep (GEMM prerequisites first so launch #6 is the big GEMM for ncu)
    k_detect<<<1, 32>>>((const unsigned*)esrc);
    k_cvt2<<<(NE + T - 1) / T, T>>>(esrc, src32, edst, dst32, NE);
    {
        size_t n = (size_t)NNODES * INF;
        k_split<<<(unsigned)((n + T - 1) / T), T>>>(x, Xhi, Xlo, n);
    }
    k_sumsplit<<<(W_L1_SZ + T - 1) / T, T>>>(Wself1, Wneigh1, b1, Whi, Wlo, bs1,
                                             W_L1_SZ, HIDF);
    k_sumsplit<<<(W_L2_SZ + T - 1) / T, T>>>(Wself2, Wneigh2, b2,
                                             Whi + W_L2_OFF, Wlo + W_L2_OFF, bs2,
                                             W_L2_SZ, OUTF);

    // 6: layer-1 GEMM, z=5 (plane0 self+bias, planes 1..4 relations)
    {
        dim3 g(HIDF / GBN, MB, 5);
        k_mma<<<g, T, GEMM_SMEM>>>(Xhi, Xlo, Whi, Wlo, Y, bs1,
                                   NNODES, HIDF, INF, W_L1_SZ, PL1);
    }

    // CSR build (overlap-agnostic: tiny vs GEMM)
    k_zeroi<<<(NREL * NNODES + T - 1) / T, T>>>(deg, NREL * NNODES);
    k_zeroi<<<(NREL * NNODES + T - 1) / T, T>>>(cursor, NREL * NNODES);
    k_degcount<<<(NE + T - 1) / T, T>>>(dst32, deg);
    k_scanA<<<NREL * NCHUNK, 1024>>>(deg, off, bsum);
    k_scanB<<<1, 32>>>(bsum);
    k_scanC<<<NREL * NCHUNK, 1024>>>(off, bsum);
    k_fill<<<(NE + T - 1) / T, T>>>(src32, dst32, off, cursor, lists);

    // gather1: aggregate + relu + bf16 split -> Hhi/Hlo
    k_gather1<<<NNODES, HIDF / 4>>>(Y, off, deg, lists, Hhi, Hlo);

    // layer-2 GEMM, z=5
    {
        dim3 g(OUTF / GBN, MB, 5);
        k_mma<<<g, T, GEMM_SMEM>>>(Hhi, Hlo, Whi + W_L2_OFF, Wlo + W_L2_OFF, Y, bs2,
                                   NNODES, OUTF, HIDF, W_L2_SZ, PL2);
    }

    // gather2 -> out
    k_gather2<<<NNODES, OUTF / 4>>>(Y, off, deg, lists, out);
}